// round 3
// baseline (speedup 1.0000x reference)
#include <cuda_runtime.h>
#include <cuda_bf16.h>
#include <math.h>

#define N_NODES 50000
#define N_EDGES 800000
#define E_TOT   850000          // edges + self loops
#define IN_DIM  128
#define HID     64
#define HEADS   4
#define F1      256             // HEADS*HID
#define OUT_DIM 16
#define N_GRAPHS 500
#define NEG_SLOPE 0.2f

// ---------------- device scratch (static, no runtime alloc) ----------------
__device__ __align__(16) float g_h[N_NODES * F1];      // post-GEMM features [N,256]
__device__ __align__(16) float g_hpost[N_NODES * HID]; // post-attention features [N,64]
__device__ __align__(16) float g_as[N_NODES * HEADS];
__device__ __align__(16) float g_ad[N_NODES * HEADS];
__device__ int   g_count[N_NODES];
__device__ int   g_rowptr[N_NODES + 1];
__device__ int   g_cursor[N_NODES];
__device__ int   g_col[E_TOT];             // src index per CSR slot
__device__ int   g_chunksum[64];
__device__ int   g_chunkoff[64];

// ---------------- packed f32x2 helpers ----------------
#define FMA_F32X2(d, a, b) \
    asm("fma.rn.f32x2 %0, %1, %2, %0;" : "+l"(d) : "l"(a), "l"(b))
#define PACK_DUP_F32X2(d, f) \
    asm("mov.b64 %0, {%1, %1};" : "=l"(d) : "f"(f))

// ============================================================================
// CSR build  (edge_index is int32: row 0 = src, row 1 = dst)
// ============================================================================
__global__ void k_zero_count() {
    int i = blockIdx.x * blockDim.x + threadIdx.x;
    if (i < N_NODES) g_count[i] = 0;
}

__global__ void k_hist(const int* __restrict__ ei) {
    int e = blockIdx.x * blockDim.x + threadIdx.x;
    if (e >= E_TOT) return;
    int dst = (e < N_EDGES) ? ei[N_EDGES + e] : (e - N_EDGES);
    atomicAdd(&g_count[dst], 1);
}

__global__ void k_scan1() {
    __shared__ int sh[1024];
    int tid = threadIdx.x;
    int i = blockIdx.x * 1024 + tid;
    int v = (i < N_NODES) ? g_count[i] : 0;
    sh[tid] = v;
    __syncthreads();
#pragma unroll
    for (int off = 1; off < 1024; off <<= 1) {
        int t = (tid >= off) ? sh[tid - off] : 0;
        __syncthreads();
        sh[tid] += t;
        __syncthreads();
    }
    if (i < N_NODES) g_rowptr[i + 1] = sh[tid];   // chunk-local inclusive
    if (tid == 1023) g_chunksum[blockIdx.x] = sh[1023];
}

__global__ void k_scan2(int nch) {
    __shared__ int s[64];
    int tid = threadIdx.x;
    int v = (tid < nch) ? g_chunksum[tid] : 0;
    s[tid] = v;
    __syncthreads();
#pragma unroll
    for (int off = 1; off < 64; off <<= 1) {
        int t = (tid >= off) ? s[tid - off] : 0;
        __syncthreads();
        s[tid] += t;
        __syncthreads();
    }
    if (tid < nch) g_chunkoff[tid] = s[tid] - v;  // exclusive
}

__global__ void k_scan3() {
    int tid = threadIdx.x;
    int i = blockIdx.x * 1024 + tid;
    if (i < N_NODES) g_rowptr[i + 1] += g_chunkoff[blockIdx.x];
    if (blockIdx.x == 0 && tid == 0) g_rowptr[0] = 0;
}

__global__ void k_cursor() {
    int i = blockIdx.x * blockDim.x + threadIdx.x;
    if (i < N_NODES) g_cursor[i] = g_rowptr[i];
}

__global__ void k_scatter(const int* __restrict__ ei) {
    int e = blockIdx.x * blockDim.x + threadIdx.x;
    if (e >= E_TOT) return;
    int src, dst;
    if (e < N_EDGES) {
        src = ei[e];
        dst = ei[N_EDGES + e];
    } else {
        src = dst = e - N_EDGES;
    }
    int p = atomicAdd(&g_cursor[dst], 1);
    g_col[p] = src;
}

// ============================================================================
// GEMM: g_h[M,256] = A[M,K] @ W[K,256]   (fp32, f32x2-packed FMA)
// BM=64, BN=128 (grid.y halves), Kc=64 chunks, TM=4, TN=8, 256 threads
// ============================================================================
template <int K, bool USE_EXT>
__global__ __launch_bounds__(256) void k_gemm256(
    const float* __restrict__ Aext, const float* __restrict__ W)
{
    __shared__ float As[64][64];     // 16 KB
    __shared__ float Bs[64][128];    // 32 KB

    const float* A = USE_EXT ? Aext : (const float*)g_hpost;

    int tid = threadIdx.x;
    int row0 = blockIdx.x * 64;
    int ncol0 = blockIdx.y * 128;

    int rg = tid >> 4;      // row group 0..15 -> rows rg*4..rg*4+3
    int cg = tid & 15;      // col group 0..15 -> cols cg*8..cg*8+7

    unsigned long long acc[4][4];
#pragma unroll
    for (int i = 0; i < 4; i++)
#pragma unroll
        for (int j = 0; j < 4; j++) acc[i][j] = 0ull;

#pragma unroll
    for (int kc = 0; kc < K; kc += 64) {
#pragma unroll
        for (int it = 0; it < 4; it++) {
            int idx = tid + it * 256;          // 1024 float4 slots
            int r = idx >> 4, c4 = idx & 15;
            int row = row0 + r;
            float4 a = (row < N_NODES)
                ? *(const float4*)(A + (long)row * K + kc + c4 * 4)
                : make_float4(0.f, 0.f, 0.f, 0.f);
            *(float4*)(&As[r][c4 * 4]) = a;
        }
#pragma unroll
        for (int it = 0; it < 8; it++) {
            int idx = tid + it * 256;          // 2048 float4 slots
            int k = idx >> 5, j4 = idx & 31;
            float4 w = *(const float4*)(W + (long)(kc + k) * 256 + ncol0 + j4 * 4);
            *(float4*)(&Bs[k][j4 * 4]) = w;
        }
        __syncthreads();

#pragma unroll 8
        for (int k = 0; k < 64; k++) {
            const unsigned long long* bp =
                (const unsigned long long*)(&Bs[k][cg * 8]);
            unsigned long long b0 = bp[0], b1 = bp[1], b2 = bp[2], b3 = bp[3];
#pragma unroll
            for (int i = 0; i < 4; i++) {
                float a = As[rg * 4 + i][k];
                unsigned long long ap;
                PACK_DUP_F32X2(ap, a);
                FMA_F32X2(acc[i][0], ap, b0);
                FMA_F32X2(acc[i][1], ap, b1);
                FMA_F32X2(acc[i][2], ap, b2);
                FMA_F32X2(acc[i][3], ap, b3);
            }
        }
        __syncthreads();
    }

#pragma unroll
    for (int i = 0; i < 4; i++) {
        int row = row0 + rg * 4 + i;
        if (row >= N_NODES) continue;
        float* cp = g_h + (long)row * 256 + ncol0 + cg * 8;
        float2 f0 = *(float2*)&acc[i][0];
        float2 f1 = *(float2*)&acc[i][1];
        float2 f2 = *(float2*)&acc[i][2];
        float2 f3 = *(float2*)&acc[i][3];
        *(float4*)(cp)     = make_float4(f0.x, f0.y, f1.x, f1.y);
        *(float4*)(cp + 4) = make_float4(f2.x, f2.y, f3.x, f3.y);
    }
}

// ============================================================================
// attn prep: as[n,h] = sum_d h[n,h*64+d]*a_src[h,d]   (one warp per node)
// ============================================================================
__global__ __launch_bounds__(256) void k_attn_prep(
    const float* __restrict__ a_src, const float* __restrict__ a_dst)
{
    int gw = (blockIdx.x * blockDim.x + threadIdx.x) >> 5;
    int lane = threadIdx.x & 31;
    if (gw >= N_NODES) return;
    int k0 = lane * 8;             // flat feature offset, head = lane/8
    const float* hp = g_h + (long)gw * F1 + k0;
    float4 p0 = *(const float4*)(hp);
    float4 p1 = *(const float4*)(hp + 4);
    float4 s0 = *(const float4*)(a_src + k0);
    float4 s1 = *(const float4*)(a_src + k0 + 4);
    float4 d0 = *(const float4*)(a_dst + k0);
    float4 d1 = *(const float4*)(a_dst + k0 + 4);
    float ps = p0.x*s0.x + p0.y*s0.y + p0.z*s0.z + p0.w*s0.w
             + p1.x*s1.x + p1.y*s1.y + p1.z*s1.z + p1.w*s1.w;
    float pd = p0.x*d0.x + p0.y*d0.y + p0.z*d0.z + p0.w*d0.w
             + p1.x*d1.x + p1.y*d1.y + p1.z*d1.z + p1.w*d1.w;
#pragma unroll
    for (int off = 1; off < 8; off <<= 1) {
        ps += __shfl_xor_sync(0xFFFFFFFF, ps, off);
        pd += __shfl_xor_sync(0xFFFFFFFF, pd, off);
    }
    if ((lane & 7) == 0) {
        g_as[gw * HEADS + (lane >> 3)] = ps;
        g_ad[gw * HEADS + (lane >> 3)] = pd;
    }
}

// ============================================================================
// GAT attention + aggregation + head-mean + bias + relu  (one warp per node)
// ============================================================================
__device__ __forceinline__ float lrelu(float v) {
    return v > 0.f ? v : NEG_SLOPE * v;
}

__global__ __launch_bounds__(256) void k_gat_attn(
    const float* __restrict__ bias)
{
    int n = (blockIdx.x * blockDim.x + threadIdx.x) >> 5;
    int lane = threadIdx.x & 31;
    if (n >= N_NODES) return;

    int beg = g_rowptr[n], end = g_rowptr[n + 1];
    float4 adv = *(const float4*)(g_ad + n * 4);
    float ad0 = adv.x, ad1 = adv.y, ad2 = adv.z, ad3 = adv.w;

    // pass 1: per-head max
    float mx0 = -INFINITY, mx1 = -INFINITY, mx2 = -INFINITY, mx3 = -INFINITY;
    for (int e = beg + lane; e < end; e += 32) {
        int s = g_col[e];
        float4 av = *(const float4*)(g_as + s * 4);
        mx0 = fmaxf(mx0, lrelu(av.x + ad0));
        mx1 = fmaxf(mx1, lrelu(av.y + ad1));
        mx2 = fmaxf(mx2, lrelu(av.z + ad2));
        mx3 = fmaxf(mx3, lrelu(av.w + ad3));
    }
#pragma unroll
    for (int off = 16; off >= 1; off >>= 1) {
        mx0 = fmaxf(mx0, __shfl_xor_sync(0xFFFFFFFF, mx0, off));
        mx1 = fmaxf(mx1, __shfl_xor_sync(0xFFFFFFFF, mx1, off));
        mx2 = fmaxf(mx2, __shfl_xor_sync(0xFFFFFFFF, mx2, off));
        mx3 = fmaxf(mx3, __shfl_xor_sync(0xFFFFFFFF, mx3, off));
    }

    // pass 2: per-head sum of exp
    float se0 = 0.f, se1 = 0.f, se2 = 0.f, se3 = 0.f;
    for (int e = beg + lane; e < end; e += 32) {
        int s = g_col[e];
        float4 av = *(const float4*)(g_as + s * 4);
        se0 += __expf(lrelu(av.x + ad0) - mx0);
        se1 += __expf(lrelu(av.y + ad1) - mx1);
        se2 += __expf(lrelu(av.z + ad2) - mx2);
        se3 += __expf(lrelu(av.w + ad3) - mx3);
    }
#pragma unroll
    for (int off = 16; off >= 1; off >>= 1) {
        se0 += __shfl_xor_sync(0xFFFFFFFF, se0, off);
        se1 += __shfl_xor_sync(0xFFFFFFFF, se1, off);
        se2 += __shfl_xor_sync(0xFFFFFFFF, se2, off);
        se3 += __shfl_xor_sync(0xFFFFFFFF, se3, off);
    }

    // pass 3: weighted aggregation; lane owns flat features lane*8..lane*8+7
    int h0 = lane >> 3;
    float myad = (h0 == 0) ? ad0 : (h0 == 1) ? ad1 : (h0 == 2) ? ad2 : ad3;
    float mymx = (h0 == 0) ? mx0 : (h0 == 1) ? mx1 : (h0 == 2) ? mx2 : mx3;
    float myinv = 1.f / ((h0 == 0) ? se0 : (h0 == 1) ? se1 : (h0 == 2) ? se2 : se3);
    int k0 = lane * 8;

    float acc[8];
#pragma unroll
    for (int k = 0; k < 8; k++) acc[k] = 0.f;

    for (int e = beg; e < end; e++) {
        int s = g_col[e];                         // uniform -> broadcast load
        float myas = g_as[s * 4 + h0];
        float alpha = __expf(lrelu(myas + myad) - mymx) * myinv;
        const float* hp = g_h + (long)s * F1 + k0;
        float4 p0 = *(const float4*)(hp);
        float4 p1 = *(const float4*)(hp + 4);
        acc[0] += alpha * p0.x; acc[1] += alpha * p0.y;
        acc[2] += alpha * p0.z; acc[3] += alpha * p0.w;
        acc[4] += alpha * p1.x; acc[5] += alpha * p1.y;
        acc[6] += alpha * p1.z; acc[7] += alpha * p1.w;
    }

    // head mean: sum lanes {l, l^8, l^16, l^24} (same within-head dim slot)
#pragma unroll
    for (int k = 0; k < 8; k++) {
        acc[k] += __shfl_xor_sync(0xFFFFFFFF, acc[k], 8);
        acc[k] += __shfl_xor_sync(0xFFFFFFFF, acc[k], 16);
    }
    if (lane < 8) {
        float* op = g_hpost + (long)n * HID + lane * 8;
#pragma unroll
        for (int k = 0; k < 8; k++) {
            float v = acc[k] * 0.25f + bias[lane * 8 + k];
            op[k] = v > 0.f ? v : 0.f;
        }
    }
}

// ============================================================================
// pool (segment mean over sorted batch) + FC  (one block per graph, 64 thr)
// ============================================================================
__device__ __forceinline__ int lowerb(const int* b, int n, int v) {
    int lo = 0, hi = n;
    while (lo < hi) {
        int m = (lo + hi) >> 1;
        if (b[m] < v) lo = m + 1; else hi = m;
    }
    return lo;
}

__global__ __launch_bounds__(64) void k_pool_fc(
    const int* __restrict__ batch,
    const float* __restrict__ fcW, const float* __restrict__ fcb,
    float* __restrict__ out)
{
    int g = blockIdx.x;
    int d = threadIdx.x;
    int lo = lowerb(batch, N_NODES, g);
    int hi = lowerb(batch, N_NODES, g + 1);
    float acc = 0.f;
    for (int i = lo; i < hi; i++) acc += g_hpost[(long)i * HID + d];
    int cnt = hi - lo;
    float inv = 1.f / (float)(cnt > 0 ? cnt : 1);
    __shared__ float sp[HID];
    sp[d] = acc * inv;
    __syncthreads();
    if (d < OUT_DIM) {
        float o = fcb[d];
#pragma unroll
        for (int k = 0; k < HID; k++) o += sp[k] * fcW[k * OUT_DIM + d];
        out[g * OUT_DIM + d] = o;
    }
}

// ============================================================================
// launcher — kernel launches ONLY (no runtime API calls; graph-capture safe)
// ============================================================================
extern "C" void kernel_launch(void* const* d_in, const int* in_sizes, int n_in,
                              void* d_out, int out_size)
{
    const float* x     = (const float*)d_in[0];
    const int*   ei    = (const int*)d_in[1];     // int32 (JAX x64 disabled)
    const int*   batch = (const int*)d_in[2];     // int32
    const float* W1    = (const float*)d_in[3];
    const float* a1s   = (const float*)d_in[4];
    const float* a1d   = (const float*)d_in[5];
    const float* b1    = (const float*)d_in[6];
    const float* W2    = (const float*)d_in[7];
    const float* a2s   = (const float*)d_in[8];
    const float* a2d   = (const float*)d_in[9];
    const float* b2    = (const float*)d_in[10];
    const float* fcW   = (const float*)d_in[11];
    const float* fcb   = (const float*)d_in[12];
    float*       out   = (float*)d_out;

    // ---- CSR build ----
    const int NCH = (N_NODES + 1023) / 1024;   // 49
    k_zero_count<<<(N_NODES + 255) / 256, 256>>>();
    k_hist<<<(E_TOT + 255) / 256, 256>>>(ei);
    k_scan1<<<NCH, 1024>>>();
    k_scan2<<<1, 64>>>(NCH);
    k_scan3<<<NCH, 1024>>>();
    k_cursor<<<(N_NODES + 255) / 256, 256>>>();
    k_scatter<<<(E_TOT + 255) / 256, 256>>>(ei);

    dim3 ggrid((N_NODES + 63) / 64, 2);

    // ---- layer 1 ----
    k_gemm256<128, true><<<ggrid, 256>>>(x, W1);
    k_attn_prep<<<(N_NODES + 7) / 8, 256>>>(a1s, a1d);
    k_gat_attn<<<(N_NODES + 7) / 8, 256>>>(b1);

    // ---- layer 2 ----
    k_gemm256<64, false><<<ggrid, 256>>>(nullptr, W2);
    k_attn_prep<<<(N_NODES + 7) / 8, 256>>>(a2s, a2d);
    k_gat_attn<<<(N_NODES + 7) / 8, 256>>>(b2);

    // ---- pool + fc ----
    k_pool_fc<<<N_GRAPHS, 64>>>(batch, fcW, fcb, out);
}

// round 4
// speedup vs baseline: 1.2045x; 1.2045x over previous
#include <cuda_runtime.h>
#include <cuda_fp16.h>
#include <math.h>

#define N_NODES 50000
#define N_EDGES 800000
#define E_TOT   850000          // edges + self loops
#define IN_DIM  128
#define HID     64
#define HEADS   4
#define F1      256             // HEADS*HID
#define OUT_DIM 16
#define N_GRAPHS 500
#define NEG_SLOPE 0.2f

// ---------------- device scratch (static, no runtime alloc) ----------------
__device__ __align__(16) __half g_h[N_NODES * F1];     // post-GEMM features [N,256], fp16
__device__ __align__(16) float g_hpost[N_NODES * HID]; // post-attention features [N,64]
__device__ __align__(16) float g_as[N_NODES * HEADS];
__device__ __align__(16) float g_ad[N_NODES * HEADS];
__device__ int   g_count[N_NODES];
__device__ int   g_rowptr[N_NODES + 1];
__device__ int   g_cursor[N_NODES];
__device__ int   g_col[E_TOT];             // src index per CSR slot
__device__ int   g_chunksum[64];
__device__ int   g_chunkoff[64];

// ---------------- packed f32x2 helpers ----------------
#define FMA_F32X2(d, a, b) \
    asm("fma.rn.f32x2 %0, %1, %2, %0;" : "+l"(d) : "l"(a), "l"(b))
#define PACK_DUP_F32X2(d, f) \
    asm("mov.b64 %0, {%1, %1};" : "=l"(d) : "f"(f))

// ============================================================================
// CSR build  (edge_index is int32: row 0 = src, row 1 = dst)
// ============================================================================
__global__ void k_zero_count() {
    int i = blockIdx.x * blockDim.x + threadIdx.x;
    if (i < N_NODES) g_count[i] = 0;
}

__global__ void k_hist(const int* __restrict__ ei) {
    int e = blockIdx.x * blockDim.x + threadIdx.x;
    if (e >= E_TOT) return;
    int dst = (e < N_EDGES) ? ei[N_EDGES + e] : (e - N_EDGES);
    atomicAdd(&g_count[dst], 1);
}

__global__ void k_scan1() {
    __shared__ int sh[1024];
    int tid = threadIdx.x;
    int i = blockIdx.x * 1024 + tid;
    int v = (i < N_NODES) ? g_count[i] : 0;
    sh[tid] = v;
    __syncthreads();
#pragma unroll
    for (int off = 1; off < 1024; off <<= 1) {
        int t = (tid >= off) ? sh[tid - off] : 0;
        __syncthreads();
        sh[tid] += t;
        __syncthreads();
    }
    if (i < N_NODES) g_rowptr[i + 1] = sh[tid];   // chunk-local inclusive
    if (tid == 1023) g_chunksum[blockIdx.x] = sh[1023];
}

__global__ void k_scan2(int nch) {
    __shared__ int s[64];
    int tid = threadIdx.x;
    int v = (tid < nch) ? g_chunksum[tid] : 0;
    s[tid] = v;
    __syncthreads();
#pragma unroll
    for (int off = 1; off < 64; off <<= 1) {
        int t = (tid >= off) ? s[tid - off] : 0;
        __syncthreads();
        s[tid] += t;
        __syncthreads();
    }
    if (tid < nch) g_chunkoff[tid] = s[tid] - v;  // exclusive
}

__global__ void k_scan3() {
    int tid = threadIdx.x;
    int i = blockIdx.x * 1024 + tid;
    if (i < N_NODES) g_rowptr[i + 1] += g_chunkoff[blockIdx.x];
    if (blockIdx.x == 0 && tid == 0) g_rowptr[0] = 0;
}

__global__ void k_cursor() {
    int i = blockIdx.x * blockDim.x + threadIdx.x;
    if (i < N_NODES) g_cursor[i] = g_rowptr[i];
}

__global__ void k_scatter(const int* __restrict__ ei) {
    int e = blockIdx.x * blockDim.x + threadIdx.x;
    if (e >= E_TOT) return;
    int src, dst;
    if (e < N_EDGES) {
        src = ei[e];
        dst = ei[N_EDGES + e];
    } else {
        src = dst = e - N_EDGES;
    }
    int p = atomicAdd(&g_cursor[dst], 1);
    g_col[p] = src;
}

// ============================================================================
// GEMM: g_h[M,256](fp16) = A[M,K](fp32) @ W[K,256](fp32), fp32 accumulate
// BM=64, BN=128 (grid.y halves), Kc=64 chunks, TM=4, TN=8, 256 threads
// Inner loop: k-step 4, LDS.128 A-slices (broadcast) + 2x LDS.128 B per k.
// ============================================================================
template <int K, bool USE_EXT>
__global__ __launch_bounds__(256) void k_gemm256(
    const float* __restrict__ Aext, const float* __restrict__ W)
{
    __shared__ float As[64][64];     // 16 KB, [row][k]
    __shared__ float Bs[64][128];    // 32 KB, [k][col]

    const float* A = USE_EXT ? Aext : (const float*)g_hpost;

    int tid = threadIdx.x;
    int row0 = blockIdx.x * 64;
    int ncol0 = blockIdx.y * 128;

    int rg = tid >> 4;      // row group 0..15 -> rows rg*4..rg*4+3
    int cg = tid & 15;      // col group 0..15 -> cols cg*8..cg*8+7

    unsigned long long acc[4][4];
#pragma unroll
    for (int i = 0; i < 4; i++)
#pragma unroll
        for (int j = 0; j < 4; j++) acc[i][j] = 0ull;

#pragma unroll
    for (int kc = 0; kc < K; kc += 64) {
#pragma unroll
        for (int it = 0; it < 4; it++) {
            int idx = tid + it * 256;          // 1024 float4 slots
            int r = idx >> 4, c4 = idx & 15;
            int row = row0 + r;
            float4 a = (row < N_NODES)
                ? *(const float4*)(A + (long)row * K + kc + c4 * 4)
                : make_float4(0.f, 0.f, 0.f, 0.f);
            *(float4*)(&As[r][c4 * 4]) = a;
        }
#pragma unroll
        for (int it = 0; it < 8; it++) {
            int idx = tid + it * 256;          // 2048 float4 slots
            int k = idx >> 5, j4 = idx & 31;
            float4 w = *(const float4*)(W + (long)(kc + k) * 256 + ncol0 + j4 * 4);
            *(float4*)(&Bs[k][j4 * 4]) = w;
        }
        __syncthreads();

#pragma unroll
        for (int k4 = 0; k4 < 64; k4 += 4) {
            float4 a4[4];
#pragma unroll
            for (int i = 0; i < 4; i++)
                a4[i] = *(const float4*)(&As[rg * 4 + i][k4]);
#pragma unroll
            for (int kk = 0; kk < 4; kk++) {
                union { float4 f; unsigned long long u[2]; } ua, ub;
                const float* brow = &Bs[k4 + kk][cg * 8];
                ua.f = *(const float4*)(brow);
                ub.f = *(const float4*)(brow + 4);
                unsigned long long b0 = ua.u[0], b1 = ua.u[1];
                unsigned long long b2 = ub.u[0], b3 = ub.u[1];
#pragma unroll
                for (int i = 0; i < 4; i++) {
                    float a = (kk == 0) ? a4[i].x : (kk == 1) ? a4[i].y
                            : (kk == 2) ? a4[i].z : a4[i].w;
                    unsigned long long ap;
                    PACK_DUP_F32X2(ap, a);
                    FMA_F32X2(acc[i][0], ap, b0);
                    FMA_F32X2(acc[i][1], ap, b1);
                    FMA_F32X2(acc[i][2], ap, b2);
                    FMA_F32X2(acc[i][3], ap, b3);
                }
            }
        }
        __syncthreads();
    }

#pragma unroll
    for (int i = 0; i < 4; i++) {
        int row = row0 + rg * 4 + i;
        if (row >= N_NODES) continue;
        __half* cp = g_h + (long)row * 256 + ncol0 + cg * 8;
        __half2 q[4];
        q[0] = __float22half2_rn(*(float2*)&acc[i][0]);
        q[1] = __float22half2_rn(*(float2*)&acc[i][1]);
        q[2] = __float22half2_rn(*(float2*)&acc[i][2]);
        q[3] = __float22half2_rn(*(float2*)&acc[i][3]);
        *(uint4*)cp = *(uint4*)q;   // 8 halves = 16B
    }
}

// ============================================================================
// attn prep: as[n,h] = sum_d h[n,h*64+d]*a_src[h,d]   (one warp per node)
// ============================================================================
__global__ __launch_bounds__(256) void k_attn_prep(
    const float* __restrict__ a_src, const float* __restrict__ a_dst)
{
    int gw = (blockIdx.x * blockDim.x + threadIdx.x) >> 5;
    int lane = threadIdx.x & 31;
    if (gw >= N_NODES) return;
    int k0 = lane * 8;             // flat feature offset, head = lane/8
    const __half* hp = g_h + (long)gw * F1 + k0;
    uint4 raw = *(const uint4*)hp;
    __half2* ph = (__half2*)&raw;
    float2 f0 = __half22float2(ph[0]);   // h[k0+0], h[k0+1]
    float2 f1 = __half22float2(ph[1]);
    float2 f2 = __half22float2(ph[2]);
    float2 f3 = __half22float2(ph[3]);
    float4 s0 = *(const float4*)(a_src + k0);
    float4 s1 = *(const float4*)(a_src + k0 + 4);
    float4 d0 = *(const float4*)(a_dst + k0);
    float4 d1 = *(const float4*)(a_dst + k0 + 4);
    float ps = f0.x*s0.x + f0.y*s0.y + f1.x*s0.z + f1.y*s0.w
             + f2.x*s1.x + f2.y*s1.y + f3.x*s1.z + f3.y*s1.w;
    float pd = f0.x*d0.x + f0.y*d0.y + f1.x*d0.z + f1.y*d0.w
             + f2.x*d1.x + f2.y*d1.y + f3.x*d1.z + f3.y*d1.w;
#pragma unroll
    for (int off = 1; off < 8; off <<= 1) {
        ps += __shfl_xor_sync(0xFFFFFFFF, ps, off);
        pd += __shfl_xor_sync(0xFFFFFFFF, pd, off);
    }
    if ((lane & 7) == 0) {
        g_as[gw * HEADS + (lane >> 3)] = ps;
        g_ad[gw * HEADS + (lane >> 3)] = pd;
    }
}

// ============================================================================
// GAT attention + aggregation + head-mean + bias + relu  (one warp per node)
// ============================================================================
__device__ __forceinline__ float lrelu(float v) {
    return v > 0.f ? v : NEG_SLOPE * v;
}

__global__ __launch_bounds__(256) void k_gat_attn(
    const float* __restrict__ bias)
{
    int n = (blockIdx.x * blockDim.x + threadIdx.x) >> 5;
    int lane = threadIdx.x & 31;
    if (n >= N_NODES) return;

    int beg = g_rowptr[n], end = g_rowptr[n + 1];
    float4 adv = *(const float4*)(g_ad + n * 4);
    float ad0 = adv.x, ad1 = adv.y, ad2 = adv.z, ad3 = adv.w;

    // pass 1: per-head max
    float mx0 = -INFINITY, mx1 = -INFINITY, mx2 = -INFINITY, mx3 = -INFINITY;
    for (int e = beg + lane; e < end; e += 32) {
        int s = g_col[e];
        float4 av = *(const float4*)(g_as + s * 4);
        mx0 = fmaxf(mx0, lrelu(av.x + ad0));
        mx1 = fmaxf(mx1, lrelu(av.y + ad1));
        mx2 = fmaxf(mx2, lrelu(av.z + ad2));
        mx3 = fmaxf(mx3, lrelu(av.w + ad3));
    }
#pragma unroll
    for (int off = 16; off >= 1; off >>= 1) {
        mx0 = fmaxf(mx0, __shfl_xor_sync(0xFFFFFFFF, mx0, off));
        mx1 = fmaxf(mx1, __shfl_xor_sync(0xFFFFFFFF, mx1, off));
        mx2 = fmaxf(mx2, __shfl_xor_sync(0xFFFFFFFF, mx2, off));
        mx3 = fmaxf(mx3, __shfl_xor_sync(0xFFFFFFFF, mx3, off));
    }

    // pass 2: per-head sum of exp
    float se0 = 0.f, se1 = 0.f, se2 = 0.f, se3 = 0.f;
    for (int e = beg + lane; e < end; e += 32) {
        int s = g_col[e];
        float4 av = *(const float4*)(g_as + s * 4);
        se0 += __expf(lrelu(av.x + ad0) - mx0);
        se1 += __expf(lrelu(av.y + ad1) - mx1);
        se2 += __expf(lrelu(av.z + ad2) - mx2);
        se3 += __expf(lrelu(av.w + ad3) - mx3);
    }
#pragma unroll
    for (int off = 16; off >= 1; off >>= 1) {
        se0 += __shfl_xor_sync(0xFFFFFFFF, se0, off);
        se1 += __shfl_xor_sync(0xFFFFFFFF, se1, off);
        se2 += __shfl_xor_sync(0xFFFFFFFF, se2, off);
        se3 += __shfl_xor_sync(0xFFFFFFFF, se3, off);
    }

    // pass 3: weighted aggregation; lane owns flat features lane*8..lane*8+7
    int h0 = lane >> 3;
    float myad = (h0 == 0) ? ad0 : (h0 == 1) ? ad1 : (h0 == 2) ? ad2 : ad3;
    float mymx = (h0 == 0) ? mx0 : (h0 == 1) ? mx1 : (h0 == 2) ? mx2 : mx3;
    float myinv = 1.f / ((h0 == 0) ? se0 : (h0 == 1) ? se1 : (h0 == 2) ? se2 : se3);
    int k0 = lane * 8;

    float acc[8];
#pragma unroll
    for (int k = 0; k < 8; k++) acc[k] = 0.f;

    for (int e = beg; e < end; e++) {
        int s = g_col[e];                         // uniform -> broadcast load
        float myas = g_as[s * 4 + h0];
        float alpha = __expf(lrelu(myas + myad) - mymx) * myinv;
        const __half* hp = g_h + (long)s * F1 + k0;
        uint4 raw = *(const uint4*)hp;            // 8 halves
        __half2* ph = (__half2*)&raw;
        float2 f0 = __half22float2(ph[0]);
        float2 f1 = __half22float2(ph[1]);
        float2 f2 = __half22float2(ph[2]);
        float2 f3 = __half22float2(ph[3]);
        acc[0] += alpha * f0.x; acc[1] += alpha * f0.y;
        acc[2] += alpha * f1.x; acc[3] += alpha * f1.y;
        acc[4] += alpha * f2.x; acc[5] += alpha * f2.y;
        acc[6] += alpha * f3.x; acc[7] += alpha * f3.y;
    }

    // head mean: sum lanes {l, l^8, l^16, l^24} (same within-head dim slot)
#pragma unroll
    for (int k = 0; k < 8; k++) {
        acc[k] += __shfl_xor_sync(0xFFFFFFFF, acc[k], 8);
        acc[k] += __shfl_xor_sync(0xFFFFFFFF, acc[k], 16);
    }
    if (lane < 8) {
        float* op = g_hpost + (long)n * HID + lane * 8;
#pragma unroll
        for (int k = 0; k < 8; k++) {
            float v = acc[k] * 0.25f + bias[lane * 8 + k];
            op[k] = v > 0.f ? v : 0.f;
        }
    }
}

// ============================================================================
// pool (segment mean over sorted batch) + FC  (one block per graph, 64 thr)
// ============================================================================
__device__ __forceinline__ int lowerb(const int* b, int n, int v) {
    int lo = 0, hi = n;
    while (lo < hi) {
        int m = (lo + hi) >> 1;
        if (b[m] < v) lo = m + 1; else hi = m;
    }
    return lo;
}

__global__ __launch_bounds__(64) void k_pool_fc(
    const int* __restrict__ batch,
    const float* __restrict__ fcW, const float* __restrict__ fcb,
    float* __restrict__ out)
{
    int g = blockIdx.x;
    int d = threadIdx.x;
    int lo = lowerb(batch, N_NODES, g);
    int hi = lowerb(batch, N_NODES, g + 1);
    float acc = 0.f;
    for (int i = lo; i < hi; i++) acc += g_hpost[(long)i * HID + d];
    int cnt = hi - lo;
    float inv = 1.f / (float)(cnt > 0 ? cnt : 1);
    __shared__ float sp[HID];
    sp[d] = acc * inv;
    __syncthreads();
    if (d < OUT_DIM) {
        float o = fcb[d];
#pragma unroll
        for (int k = 0; k < HID; k++) o += sp[k] * fcW[k * OUT_DIM + d];
        out[g * OUT_DIM + d] = o;
    }
}

// ============================================================================
// launcher — kernel launches ONLY (no runtime API calls; graph-capture safe)
// ============================================================================
extern "C" void kernel_launch(void* const* d_in, const int* in_sizes, int n_in,
                              void* d_out, int out_size)
{
    const float* x     = (const float*)d_in[0];
    const int*   ei    = (const int*)d_in[1];     // int32 (JAX x64 disabled)
    const int*   batch = (const int*)d_in[2];     // int32
    const float* W1    = (const float*)d_in[3];
    const float* a1s   = (const float*)d_in[4];
    const float* a1d   = (const float*)d_in[5];
    const float* b1    = (const float*)d_in[6];
    const float* W2    = (const float*)d_in[7];
    const float* a2s   = (const float*)d_in[8];
    const float* a2d   = (const float*)d_in[9];
    const float* b2    = (const float*)d_in[10];
    const float* fcW   = (const float*)d_in[11];
    const float* fcb   = (const float*)d_in[12];
    float*       out   = (float*)d_out;

    // ---- CSR build ----
    const int NCH = (N_NODES + 1023) / 1024;   // 49
    k_zero_count<<<(N_NODES + 255) / 256, 256>>>();
    k_hist<<<(E_TOT + 255) / 256, 256>>>(ei);
    k_scan1<<<NCH, 1024>>>();
    k_scan2<<<1, 64>>>(NCH);
    k_scan3<<<NCH, 1024>>>();
    k_cursor<<<(N_NODES + 255) / 256, 256>>>();
    k_scatter<<<(E_TOT + 255) / 256, 256>>>(ei);

    dim3 ggrid((N_NODES + 63) / 64, 2);

    // ---- layer 1 ----
    k_gemm256<128, true><<<ggrid, 256>>>(x, W1);
    k_attn_prep<<<(N_NODES + 7) / 8, 256>>>(a1s, a1d);
    k_gat_attn<<<(N_NODES + 7) / 8, 256>>>(b1);

    // ---- layer 2 ----
    k_gemm256<64, false><<<ggrid, 256>>>(nullptr, W2);
    k_attn_prep<<<(N_NODES + 7) / 8, 256>>>(a2s, a2d);
    k_gat_attn<<<(N_NODES + 7) / 8, 256>>>(b2);

    // ---- pool + fc ----
    k_pool_fc<<<N_GRAPHS, 64>>>(batch, fcW, fcb, out);
}